// round 16
// baseline (speedup 1.0000x reference)
#include <cuda_runtime.h>
#include <cuda_bf16.h>
#include <cstdint>

#define CCH   64
#define HW    441
#define HWP   448
#define NROW  448
#define B1MAX 32
#define B2MAX 25
#define NHALF 224

// tcgen05 only exists on 'a'-suffix targets (proven live in R6/R8).
#if defined(__CUDA_ARCH__) && (defined(__CUDA_ARCH_FEAT_SM103_ALL) || \
                               defined(__CUDA_ARCH_FEAT_SM100_ALL) || \
                               defined(__CUDA_ARCH_FEAT_SM101_ALL))
#define HAS_TC 1
#else
#define HAS_TC 0
#endif

// ---------------- GMEM scratch ----------------
__device__ float g_qh[B1MAX * CCH * HWP];            // fp32 channel-major (non-'a' image only)
__device__ float g_sh[B2MAX * CCH * HWP];
__device__ __align__(16) __nv_bfloat16 g_qhi[B1MAX * NROW * CCH];  // [b][row][c]
__device__ __align__(16) __nv_bfloat16 g_qlo[B1MAX * NROW * CCH];
__device__ __align__(16) __nv_bfloat16 g_shi[B2MAX * NROW * CCH];
__device__ __align__(16) __nv_bfloat16 g_slo[B2MAX * NROW * CCH];
__device__ float g_part[B1MAX * B2MAX * 2];          // per half-pair partial sums

// ---------------- pair-kernel SMEM layout (bytes) ----------------
#define SM_TPTR   0
#define SM_FULL0  16
#define SM_FULL1  24
#define SM_EMPTY0 32
#define SM_EMPTY1 40
#define SM_QRDY0  48
#define SM_QRDY1  56
#define SM_WSUM   64
#define SM_MERGE  128                      // 128 rows * 3 floats
#define SM_SHI    2048                     // 57344
#define SM_SLO    (SM_SHI + 57344)
#define SM_QB     (SM_SLO + 57344)         // 2 bufs x (16384 hi + 16384 lo)
#define SM_TOTAL  (SM_QB + 65536)          // 182272

#define SWZ(o) ((o) ^ ((((unsigned)(o)) >> 3) & 0x70u))

// idesc: kind::f16, dtype=F32, atype=btype=BF16, N=224, M=128
#define MMA_IDESC ((1u<<4) | (1u<<7) | (1u<<10) | ((NHALF/8)<<17) | ((128/16)<<24))

#define NEGINF_BITS 0xFF7FFFFFu            // -FLT_MAX

__device__ __forceinline__ void ins3(float& t0, float& t1, float& t2, float v) {
    float a0 = fmaxf(t0, v);
    float m0 = fminf(t0, v);
    float a1 = fmaxf(t1, m0);
    float m1 = fminf(t1, m0);
    float a2 = fmaxf(t2, m1);
    t0 = a0; t1 = a1; t2 = a2;
}

#if HAS_TC
// ---------------- tcgen05 helpers ----------------
__device__ __forceinline__ uint64_t make_desc(uint32_t addr) {
    const uint64_t base = (uint64_t(2) << 61) | (uint64_t(1) << 46)
                        | (uint64_t(64) << 32) | (uint64_t(1) << 16);
    return base | ((uint64_t)(addr >> 4) & 0x3FFFull);
}
__device__ __forceinline__ uint32_t smem_u32(const void* p) {
    uint32_t a;
    asm("{ .reg .u64 t; cvta.to.shared.u64 t, %1; cvt.u32.u64 %0, t; }" : "=r"(a) : "l"(p));
    return a;
}
__device__ __forceinline__ uint32_t elect_one() {
    uint32_t pred;
    asm volatile("{ .reg .pred p; elect.sync _|p, 0xFFFFFFFF; selp.b32 %0, 1, 0, p; }" : "=r"(pred));
    return pred;
}
__device__ __forceinline__ void mma_f16_ss(uint32_t d, uint64_t ad, uint64_t bd,
                                           uint32_t idesc, uint32_t en) {
    asm volatile(
        "{\n\t.reg .pred p;\n\tsetp.ne.u32 p, %5, 0;\n\t"
        "tcgen05.mma.cta_group::1.kind::f16 [%0], %1, %2, %3, {%4, %4, %4, %4}, p;\n\t}"
        :: "r"(d), "l"(ad), "l"(bd), "r"(idesc), "r"(0u), "r"(en) : "memory");
}
__device__ __forceinline__ void mbar_init(uint32_t a, uint32_t cnt) {
    asm volatile("mbarrier.init.shared.b64 [%0], %1;" :: "r"(a), "r"(cnt) : "memory");
}
__device__ __forceinline__ void mbar_wait(uint32_t a, uint32_t par) {
    asm volatile(
        "{\n\t.reg .pred P;\n\tW_%=:\n\t"
        "mbarrier.try_wait.parity.acquire.cta.shared::cta.b64 P, [%0], %1, 0x989680;\n\t"
        "@P bra.uni D_%=;\n\tbra.uni W_%=;\n\tD_%=:\n\t}"
        :: "r"(a), "r"(par) : "memory");
}
__device__ __forceinline__ void mbar_arrive(uint32_t a) {
    asm volatile("mbarrier.arrive.shared.b64 _, [%0];" :: "r"(a) : "memory");
}
__device__ __forceinline__ void tc_commit(uint32_t mbar) {
    asm volatile(
        "tcgen05.commit.cta_group::1.mbarrier::arrive::one.shared::cluster.b64 [%0];"
        :: "r"(mbar) : "memory");
}
#define TC_WAIT_LD()      asm volatile("tcgen05.wait::ld.sync.aligned;" ::: "memory")
#define TC_FENCE_AFTER()  asm volatile("tcgen05.fence::after_thread_sync;" ::: "memory")
#define TC_FENCE_BEFORE() asm volatile("tcgen05.fence::before_thread_sync;" ::: "memory")
#define FENCE_ASYNC()     asm volatile("fence.proxy.async.shared::cta;" ::: "memory")
#define BAR_CONS()        asm volatile("bar.sync 1, 256;" ::: "memory")

#define LDTM_X32(r, a) \
    asm volatile("tcgen05.ld.sync.aligned.32x32b.x32.b32 " \
        "{%0,%1,%2,%3,%4,%5,%6,%7,%8,%9,%10,%11,%12,%13,%14,%15," \
        "%16,%17,%18,%19,%20,%21,%22,%23,%24,%25,%26,%27,%28,%29,%30,%31}, [%32];" \
        : "=r"((r)[0]),"=r"((r)[1]),"=r"((r)[2]),"=r"((r)[3]),"=r"((r)[4]),"=r"((r)[5]), \
          "=r"((r)[6]),"=r"((r)[7]),"=r"((r)[8]),"=r"((r)[9]),"=r"((r)[10]),"=r"((r)[11]), \
          "=r"((r)[12]),"=r"((r)[13]),"=r"((r)[14]),"=r"((r)[15]),"=r"((r)[16]),"=r"((r)[17]), \
          "=r"((r)[18]),"=r"((r)[19]),"=r"((r)[20]),"=r"((r)[21]),"=r"((r)[22]),"=r"((r)[23]), \
          "=r"((r)[24]),"=r"((r)[25]),"=r"((r)[26]),"=r"((r)[27]),"=r"((r)[28]),"=r"((r)[29]), \
          "=r"((r)[30]),"=r"((r)[31]) : "r"(a))

#define LDTM_X16(r, a) \
    asm volatile("tcgen05.ld.sync.aligned.32x32b.x16.b32 " \
        "{%0,%1,%2,%3,%4,%5,%6,%7,%8,%9,%10,%11,%12,%13,%14,%15}, [%16];" \
        : "=r"((r)[0]),"=r"((r)[1]),"=r"((r)[2]),"=r"((r)[3]),"=r"((r)[4]),"=r"((r)[5]), \
          "=r"((r)[6]),"=r"((r)[7]),"=r"((r)[8]),"=r"((r)[9]),"=r"((r)[10]),"=r"((r)[11]), \
          "=r"((r)[12]),"=r"((r)[13]),"=r"((r)[14]),"=r"((r)[15]) : "r"(a))

// Stage support tile (hi+lo) SW128-swizzled; any thread count.
__device__ __forceinline__ void stage_S(char* sm, int b2, int tid, int nthr) {
    const uint4* shg = (const uint4*)g_shi + (size_t)b2 * NROW * 8;
    const uint4* slg = (const uint4*)g_slo + (size_t)b2 * NROW * 8;
    for (int k = tid; k < NROW * 8; k += nthr) {
        uint32_t dst = SWZ((uint32_t)k * 16);
        *(uint4*)(sm + SM_SHI + dst) = shg[k];
        *(uint4*)(sm + SM_SLO + dst) = slg[k];
    }
}
// Stage one 128-row Q tile (hi+lo, global tile 0..3) into buffer buf; 256 threads.
__device__ __forceinline__ void stage_Q(char* sm, int b1, int tile, int buf, int tid) {
    const uint4* qhg = (const uint4*)g_qhi + (size_t)b1 * NROW * 8;
    const uint4* qlg = (const uint4*)g_qlo + (size_t)b1 * NROW * 8;
    char* qh = sm + SM_QB + buf * 32768;
    char* ql = qh + 16384;
    for (int k = tid; k < 128 * 8; k += 256) {
        int grow = tile * 128 + (k >> 3);
        uint4 vh = make_uint4(0u, 0u, 0u, 0u), vl = vh;
        if (grow < NROW) { vh = qhg[grow * 8 + (k & 7)]; vl = qlg[grow * 8 + (k & 7)]; }
        uint32_t dst = SWZ((uint32_t)k * 16);
        *(uint4*)(qh + dst) = vh;
        *(uint4*)(ql + dst) = vl;
    }
}
// Epilogue over one 224-col half. Batched LDTM under ONE wait (proven safe by
// the R9/R10 output identity), then EARLY EMPTY-ARRIVE: the D half is free the
// moment wait::ld retires (values live in registers), so the producer's next
// MMA into this half overlaps our FMNMX drain instead of stalling behind it.
__device__ __forceinline__ void epi_half_early(uint32_t tmem, int h, int wid,
                                               uint32_t empty_addr,
                                               float& t0, float& t1, float& t2) {
    const uint32_t base = tmem + h * NHALF + ((wid >= 4) ? 112 : 0);
    uint32_t r[112];
    LDTM_X32(r,      base);
    LDTM_X32(r + 32, base + 32);
    LDTM_X32(r + 64, base + 64);
    LDTM_X16(r + 96, base + 96);
    TC_WAIT_LD();
    TC_FENCE_BEFORE();
    __syncwarp();
    if (elect_one()) mbar_arrive(empty_addr);
    if ((h == 1) && (wid >= 4)) {           // global cols 441..447 invalid
        #pragma unroll
        for (int i = 105; i < 112; i++) r[i] = NEGINF_BITS;
    }
    #pragma unroll
    for (int i = 0; i < 112; i++) ins3(t0, t1, t2, __uint_as_float(r[i]));
}
#endif  // HAS_TC

// ---------------------------------------------------------------------------
// Prologue: fused over both batches (grid = B1+B2). One CTA per image.
// ---------------------------------------------------------------------------
__global__ void __launch_bounds__(256, 1)
normalize_pro(const float* __restrict__ x1, const float* __restrict__ m1, int B1,
              const float* __restrict__ x2, const float* __restrict__ m2) {
    extern __shared__ float sp[];              // [64*441] + scales[448]
    const int bg = blockIdx.x, tid = threadIdx.x;
    const bool isq = (bg < B1);
    const int b = isq ? bg : bg - B1;
    const float* x  = isq ? x1 : x2;
    const float* mk = isq ? m1 : m2;
    __nv_bfloat16* hi = isq ? g_qhi : g_shi;
    __nv_bfloat16* lo = isq ? g_qlo : g_slo;
    float* scl = sp + CCH * HW;

    const float4* src = (const float4*)(x + (size_t)b * CCH * HW);
    float4* d4 = (float4*)sp;
    for (int k = tid; k < CCH * HW / 4; k += 256) d4[k] = src[k];
    __syncthreads();

    for (int i = tid; i < HW; i += 256) {
        float ss = 0.f;
        #pragma unroll
        for (int c = 0; c < CCH; c++) { float v = sp[c * HW + i]; ss += v * v; }
        scl[i] = mk[b * HW + i] * rsqrtf(ss);
    }
    __syncthreads();

    // bf16 hi/lo row-major [row][c], 16B chunks, coalesced
    for (int k = tid; k < NROW * 8; k += 256) {
        int row = k >> 3, c0 = (k & 7) * 8;
        uint4 vh, vl;
        __nv_bfloat16* ah = (__nv_bfloat16*)&vh;
        __nv_bfloat16* al = (__nv_bfloat16*)&vl;
        if (row < HW) {
            float s = scl[row];
            #pragma unroll
            for (int j = 0; j < 8; j++) {
                float v = sp[(c0 + j) * HW + row] * s;
                __nv_bfloat16 h = __float2bfloat16(v);
                ah[j] = h;
                al[j] = __float2bfloat16(v - __bfloat162float(h));
            }
        } else {
            vh = make_uint4(0u, 0u, 0u, 0u); vl = vh;
        }
        *(uint4*)(hi + ((size_t)b * NROW + row) * CCH + c0) = vh;
        *(uint4*)(lo + ((size_t)b * NROW + row) * CCH + c0) = vl;
    }

#if !HAS_TC
    // fp32 channel-major padded (fallback image only)
    float* f32 = isq ? g_qh : g_sh;
    for (int k = tid; k < CCH * HWP; k += 256) {
        int c = k / HWP, i = k - c * HWP;
        float v = (i < HW) ? sp[c * HW + i] * scl[i] : 0.f;
        f32[(size_t)b * CCH * HWP + k] = v;
    }
#endif
}

// ---------------------------------------------------------------------------
// Persistent pair kernel over HALF-PAIR units (2 M-tiles each).
// 288 threads: 8 consumer warps + 1 producer warp. Partial sums -> g_part[u].
// Pair order is b2-major: p = b2*B1 + b1 (S-tile reuse).
// ---------------------------------------------------------------------------
__global__ void __launch_bounds__(288, 1)
pair_kernel(int B1, int B2, int nunit, int ncta) {
#if HAS_TC
    extern __shared__ __align__(1024) char sm[];
    const uint32_t smb = smem_u32(sm);
    const int tid = threadIdx.x, lane = tid & 31, wid = tid >> 5;
    const int cta = blockIdx.x;
    const int u0 = (int)((long long)cta * nunit / ncta);
    const int u1 = (int)((long long)(cta + 1) * nunit / ncta);
    if (u0 >= u1) return;

    if (wid == 8) {
        asm volatile("tcgen05.alloc.cta_group::1.sync.aligned.shared::cta.b32 [%0], %1;"
                     :: "r"(smb + SM_TPTR), "r"(512u) : "memory");
        asm volatile("tcgen05.relinquish_alloc_permit.cta_group::1.sync.aligned;");
    }
    if (tid == 0) {
        mbar_init(smb + SM_FULL0, 1);  mbar_init(smb + SM_FULL1, 1);
        mbar_init(smb + SM_EMPTY0, 8); mbar_init(smb + SM_EMPTY1, 8);
        mbar_init(smb + SM_QRDY0, 8);  mbar_init(smb + SM_QRDY1, 8);
    }
    __syncthreads();
    uint32_t tmem;
    asm volatile("ld.shared.b32 %0, [%1];" : "=r"(tmem) : "r"(smb + SM_TPTR));

    // Initial staging
    int prevb2 = (u0 >> 1) / B1;
    stage_S(sm, prevb2, tid, 288);
    if (wid < 8) stage_Q(sm, (u0 >> 1) % B1, 2 * (u0 & 1), 0, tid);
    FENCE_ASYNC();
    __syncthreads();
    if (wid < 8 && elect_one()) mbar_arrive(smb + SM_QRDY0);

    int phF0 = 0, phF1 = 0;                 // consumer full waits
    int phE0 = 1, phE1 = 1;                 // producer empty waits (flipped start)
    int phQ0 = 0, phQ1 = 0;                 // producer qready waits
    float tsum = 0.f;

    for (int u = u0; u < u1; ++u) {
        const int p = u >> 1, h = u & 1;
        const int b2 = p / B1;
        if (u > u0 && b2 != prevb2) {
            __syncthreads();                 // consumers passed last FULL1 => MMAs done
            stage_S(sm, b2, tid, 288);
            FENCE_ASYNC();
            __syncthreads();
        }
        prevb2 = b2;

        if (wid == 8) {
            // -------- producer: tiles 2h, 2h+1 --------
            for (int t = 0; t < 2; t++) {
                mbar_wait(smb + (t ? SM_QRDY1 : SM_QRDY0), t ? phQ1 : phQ0);
                if (t) phQ1 ^= 1; else phQ0 ^= 1;
                const uint64_t AH = make_desc(smb + SM_QB + t * 32768);
                const uint64_t AL = make_desc(smb + SM_QB + t * 32768 + 16384);
                const uint64_t BH = make_desc(smb + SM_SHI);
                const uint64_t BL = make_desc(smb + SM_SLO);
                #pragma unroll
                for (int h2 = 0; h2 < 2; h2++) {
                    mbar_wait(smb + (h2 ? SM_EMPTY1 : SM_EMPTY0), h2 ? phE1 : phE0);
                    if (h2) phE1 ^= 1; else phE0 ^= 1;
                    TC_FENCE_AFTER();
                    if (elect_one()) {
                        const uint64_t boff = (uint64_t)h2 * 1792;
                        const uint32_t d = tmem + h2 * NHALF;
                        uint64_t pa[3] = { AH, AH, AL };
                        uint64_t pb[3] = { BH, BL, BH };
                        int first = 1;
                        #pragma unroll
                        for (int pp = 0; pp < 3; pp++)
                            #pragma unroll
                            for (int k = 0; k < 4; k++) {
                                mma_f16_ss(d, pa[pp] + k * 2, pb[pp] + boff + k * 2,
                                           MMA_IDESC, first ? 0u : 1u);
                                first = 0;
                            }
                        tc_commit(smb + (h2 ? SM_FULL1 : SM_FULL0));
                    }
                }
            }
        } else {
            // -------- consumers: tiles 2h, 2h+1 --------
            for (int t = 0; t < 2; t++) {
                const int gtile = 2 * h + t;
                float t0 = -1e30f, t1 = -1e30f, t2 = -1e30f;
                // half 0 (EMPTY0 arrive happens inside, right after wait::ld)
                mbar_wait(smb + SM_FULL0, phF0); phF0 ^= 1;
                TC_FENCE_AFTER();
                epi_half_early(tmem, 0, wid, smb + SM_EMPTY0, t0, t1, t2);
                // staging slot: next tile of this unit, or next unit's first tile
                {
                    const bool hasnext = (t == 0) || (u + 1 < u1);
                    if (hasnext) {
                        const int nu = (t == 0) ? u : u + 1;
                        const int ntile = (t == 0) ? (2 * h + 1) : 2 * (nu & 1);
                        const int nb1 = (nu >> 1) % B1;
                        stage_Q(sm, nb1, ntile, t ^ 1, tid);
                        FENCE_ASYNC();
                        __syncwarp();
                        if (elect_one()) mbar_arrive(smb + ((t ^ 1) ? SM_QRDY1 : SM_QRDY0));
                    }
                }
                // half 1 (EMPTY1 arrive inside)
                mbar_wait(smb + SM_FULL1, phF1); phF1 ^= 1;
                TC_FENCE_AFTER();
                epi_half_early(tmem, 1, wid, smb + SM_EMPTY1, t0, t1, t2);
                // merge column-halves per row
                float* mg = (float*)(sm + SM_MERGE);
                const int r = (wid & 3) * 32 + lane;
                if (wid >= 4) { mg[r * 3] = t0; mg[r * 3 + 1] = t1; mg[r * 3 + 2] = t2; }
                BAR_CONS();
                if (wid < 4) {
                    ins3(t0, t1, t2, mg[r * 3]);
                    ins3(t0, t1, t2, mg[r * 3 + 1]);
                    ins3(t0, t1, t2, mg[r * 3 + 2]);
                    const int grow = gtile * 128 + r;
                    if (grow < HW) tsum += t0 + t1 + t2;
                }
                BAR_CONS();
            }
            // unit output -> g_part[u]
            if (wid < 4) {
                float s = tsum;
                #pragma unroll
                for (int off = 16; off; off >>= 1) s += __shfl_xor_sync(0xffffffffu, s, off);
                if (lane == 0) ((float*)(sm + SM_WSUM))[wid] = s;
            }
            BAR_CONS();
            if (tid == 0) {
                const float* ws = (const float*)(sm + SM_WSUM);
                g_part[u] = ws[0] + ws[1] + ws[2] + ws[3];
            }
            BAR_CONS();
            tsum = 0.f;
        }
    }

    __syncthreads();
    if (wid == 8) {
        asm volatile("tcgen05.dealloc.cta_group::1.sync.aligned.b32 %0, %1;"
                     :: "r"(tmem), "r"(512u));
    }

#else  // ---------------- correctness-only fallback (never selected at runtime) ----------------
    __shared__ float red[288];
    const int tid = threadIdx.x;
    const int cta = blockIdx.x;
    const int u0 = (int)((long long)cta * nunit / ncta);
    const int u1 = (int)((long long)(cta + 1) * nunit / ncta);
    for (int u = u0; u < u1; ++u) {
        const int p = u >> 1, h = u & 1;
        const int b2 = p / B1, b1 = p - b2 * B1;
        const float* qg = g_qh + (size_t)b1 * CCH * HWP;
        const float* sg = g_sh + (size_t)b2 * CCH * HWP;
        const int r0 = h * 256, r1 = (h * 256 + 256 < HW) ? h * 256 + 256 : HW;
        float part = 0.f;
        for (int r = r0 + tid; r < r1; r += blockDim.x) {
            float t0 = -1e30f, t1 = -1e30f, t2 = -1e30f;
            for (int j = 0; j < HW; j++) {
                float d = 0.f;
                for (int c = 0; c < CCH; c++) d += qg[c * HWP + r] * sg[c * HWP + j];
                ins3(t0, t1, t2, d);
            }
            part += t0 + t1 + t2;
        }
        red[tid] = part;
        __syncthreads();
        if (tid == 0) {
            float s = 0.f;
            for (int k = 0; k < (int)blockDim.x; k++) s += red[k];
            g_part[u] = s;
        }
        __syncthreads();
    }
#endif
}

// ---------------------------------------------------------------------------
// Final: units are b2-major (p = b2*B1 + b1); output is out[b1*B2 + b2].
// (R9/R10 bug was writing out[p] — transposed output.)
// ---------------------------------------------------------------------------
__global__ void sum_units(float* __restrict__ out, int B1, int B2, int npair) {
    int p = blockIdx.x * blockDim.x + threadIdx.x;
    if (p < npair) {
        int b2 = p / B1, b1 = p - b2 * B1;
        out[b1 * B2 + b2] = g_part[2 * p] + g_part[2 * p + 1];
    }
}

// ---------------------------------------------------------------------------
// Launch
// ---------------------------------------------------------------------------
extern "C" void kernel_launch(void* const* d_in, const int* in_sizes, int n_in,
                              void* d_out, int out_size) {
    const float* x1 = (const float*)d_in[0];
    const float* x2 = (const float*)d_in[1];
    const float* m1 = (const float*)d_in[2];
    const float* m2 = (const float*)d_in[3];
    float* out = (float*)d_out;

    int B1 = in_sizes[0] / (CCH * HW);
    int B2 = in_sizes[1] / (CCH * HW);
    if (B1 > B1MAX) B1 = B1MAX;
    if (B2 > B2MAX) B2 = B2MAX;

    const int pro_smem = (CCH * HW + HWP) * (int)sizeof(float);   // 114688
    cudaFuncSetAttribute(normalize_pro,
                         cudaFuncAttributeMaxDynamicSharedMemorySize, pro_smem);
    normalize_pro<<<B1 + B2, 256, pro_smem>>>(x1, m1, B1, x2, m2);

    const int npair = B1 * B2;
    const int nunit = npair * 2;
    int ncta = nunit < 148 ? nunit : 148;
    cudaFuncSetAttribute(pair_kernel,
                         cudaFuncAttributeMaxDynamicSharedMemorySize, SM_TOTAL);
    pair_kernel<<<ncta, 288, SM_TOTAL>>>(B1, B2, nunit, ncta);

    sum_units<<<(npair + 255) / 256, 256>>>(out, B1, B2, npair);
}

// round 17
// speedup vs baseline: 1.0359x; 1.0359x over previous
#include <cuda_runtime.h>
#include <cuda_bf16.h>
#include <cstdint>

#define CCH   64
#define HW    441
#define HWP   448
#define NROW  448
#define B1MAX 32
#define B2MAX 25
#define NHALF 224

// tcgen05 only exists on 'a'-suffix targets (proven live in R6/R8).
#if defined(__CUDA_ARCH__) && (defined(__CUDA_ARCH_FEAT_SM103_ALL) || \
                               defined(__CUDA_ARCH_FEAT_SM100_ALL) || \
                               defined(__CUDA_ARCH_FEAT_SM101_ALL))
#define HAS_TC 1
#else
#define HAS_TC 0
#endif

// ---------------- GMEM scratch ----------------
__device__ float g_qh[B1MAX * CCH * HWP];            // fp32 channel-major (non-'a' image only)
__device__ float g_sh[B2MAX * CCH * HWP];
__device__ __align__(16) __nv_bfloat16 g_qhi[B1MAX * NROW * CCH];  // [b][row][c]
__device__ __align__(16) __nv_bfloat16 g_qlo[B1MAX * NROW * CCH];
__device__ __align__(16) __nv_bfloat16 g_shi[B2MAX * NROW * CCH];
__device__ __align__(16) __nv_bfloat16 g_slo[B2MAX * NROW * CCH];
__device__ float g_part[B1MAX * B2MAX * 2];          // per half-pair partial sums

// ---------------- pair-kernel SMEM layout (bytes) ----------------
#define SM_TPTR   0
#define SM_FULL0  16
#define SM_FULL1  24
#define SM_EMPTY0 32
#define SM_EMPTY1 40
#define SM_QRDY0  48
#define SM_QRDY1  56
#define SM_WSUM   64
#define SM_MERGE  128                      // 128 rows * 3 floats
#define SM_SHI    2048                     // 57344
#define SM_SLO    (SM_SHI + 57344)
#define SM_QB     (SM_SLO + 57344)         // 2 bufs x (16384 hi + 16384 lo)
#define SM_TOTAL  (SM_QB + 65536)          // 182272

#define SWZ(o) ((o) ^ ((((unsigned)(o)) >> 3) & 0x70u))

// idesc: kind::f16, dtype=F32, atype=btype=BF16, N=224, M=128
#define MMA_IDESC ((1u<<4) | (1u<<7) | (1u<<10) | ((NHALF/8)<<17) | ((128/16)<<24))

#define NEGINF_BITS 0xFF7FFFFFu            // -FLT_MAX

__device__ __forceinline__ void ins3(float& t0, float& t1, float& t2, float v) {
    float a0 = fmaxf(t0, v);
    float m0 = fminf(t0, v);
    float a1 = fmaxf(t1, m0);
    float m1 = fminf(t1, m0);
    float a2 = fmaxf(t2, m1);
    t0 = a0; t1 = a1; t2 = a2;
}

#if HAS_TC
// ---------------- tcgen05 helpers ----------------
__device__ __forceinline__ uint64_t make_desc(uint32_t addr) {
    const uint64_t base = (uint64_t(2) << 61) | (uint64_t(1) << 46)
                        | (uint64_t(64) << 32) | (uint64_t(1) << 16);
    return base | ((uint64_t)(addr >> 4) & 0x3FFFull);
}
__device__ __forceinline__ uint32_t smem_u32(const void* p) {
    uint32_t a;
    asm("{ .reg .u64 t; cvta.to.shared.u64 t, %1; cvt.u32.u64 %0, t; }" : "=r"(a) : "l"(p));
    return a;
}
__device__ __forceinline__ uint32_t elect_one() {
    uint32_t pred;
    asm volatile("{ .reg .pred p; elect.sync _|p, 0xFFFFFFFF; selp.b32 %0, 1, 0, p; }" : "=r"(pred));
    return pred;
}
__device__ __forceinline__ void mma_f16_ss(uint32_t d, uint64_t ad, uint64_t bd,
                                           uint32_t idesc, uint32_t en) {
    asm volatile(
        "{\n\t.reg .pred p;\n\tsetp.ne.u32 p, %5, 0;\n\t"
        "tcgen05.mma.cta_group::1.kind::f16 [%0], %1, %2, %3, {%4, %4, %4, %4}, p;\n\t}"
        :: "r"(d), "l"(ad), "l"(bd), "r"(idesc), "r"(0u), "r"(en) : "memory");
}
__device__ __forceinline__ void mbar_init(uint32_t a, uint32_t cnt) {
    asm volatile("mbarrier.init.shared.b64 [%0], %1;" :: "r"(a), "r"(cnt) : "memory");
}
__device__ __forceinline__ void mbar_wait(uint32_t a, uint32_t par) {
    asm volatile(
        "{\n\t.reg .pred P;\n\tW_%=:\n\t"
        "mbarrier.try_wait.parity.acquire.cta.shared::cta.b64 P, [%0], %1, 0x989680;\n\t"
        "@P bra.uni D_%=;\n\tbra.uni W_%=;\n\tD_%=:\n\t}"
        :: "r"(a), "r"(par) : "memory");
}
__device__ __forceinline__ void mbar_arrive(uint32_t a) {
    asm volatile("mbarrier.arrive.shared.b64 _, [%0];" :: "r"(a) : "memory");
}
__device__ __forceinline__ void tc_commit(uint32_t mbar) {
    asm volatile(
        "tcgen05.commit.cta_group::1.mbarrier::arrive::one.shared::cluster.b64 [%0];"
        :: "r"(mbar) : "memory");
}
#define TC_WAIT_LD()      asm volatile("tcgen05.wait::ld.sync.aligned;" ::: "memory")
#define TC_FENCE_AFTER()  asm volatile("tcgen05.fence::after_thread_sync;" ::: "memory")
#define TC_FENCE_BEFORE() asm volatile("tcgen05.fence::before_thread_sync;" ::: "memory")
#define FENCE_ASYNC()     asm volatile("fence.proxy.async.shared::cta;" ::: "memory")
#define BAR_CONS()        asm volatile("bar.sync 1, 256;" ::: "memory")
// Pin t0..t2 computation between surrounding volatile asm ops (prevents ptxas
// from sinking the FMNMX chain past the next LDTM/wait — the overlap lever).
#define PIN3(t0, t1, t2)  asm volatile("" : "+f"(t0), "+f"(t1), "+f"(t2))

#define LDTM_X32(r, a) \
    asm volatile("tcgen05.ld.sync.aligned.32x32b.x32.b32 " \
        "{%0,%1,%2,%3,%4,%5,%6,%7,%8,%9,%10,%11,%12,%13,%14,%15," \
        "%16,%17,%18,%19,%20,%21,%22,%23,%24,%25,%26,%27,%28,%29,%30,%31}, [%32];" \
        : "=r"((r)[0]),"=r"((r)[1]),"=r"((r)[2]),"=r"((r)[3]),"=r"((r)[4]),"=r"((r)[5]), \
          "=r"((r)[6]),"=r"((r)[7]),"=r"((r)[8]),"=r"((r)[9]),"=r"((r)[10]),"=r"((r)[11]), \
          "=r"((r)[12]),"=r"((r)[13]),"=r"((r)[14]),"=r"((r)[15]),"=r"((r)[16]),"=r"((r)[17]), \
          "=r"((r)[18]),"=r"((r)[19]),"=r"((r)[20]),"=r"((r)[21]),"=r"((r)[22]),"=r"((r)[23]), \
          "=r"((r)[24]),"=r"((r)[25]),"=r"((r)[26]),"=r"((r)[27]),"=r"((r)[28]),"=r"((r)[29]), \
          "=r"((r)[30]),"=r"((r)[31]) : "r"(a))

#define LDTM_X16(r, a) \
    asm volatile("tcgen05.ld.sync.aligned.32x32b.x16.b32 " \
        "{%0,%1,%2,%3,%4,%5,%6,%7,%8,%9,%10,%11,%12,%13,%14,%15}, [%16];" \
        : "=r"((r)[0]),"=r"((r)[1]),"=r"((r)[2]),"=r"((r)[3]),"=r"((r)[4]),"=r"((r)[5]), \
          "=r"((r)[6]),"=r"((r)[7]),"=r"((r)[8]),"=r"((r)[9]),"=r"((r)[10]),"=r"((r)[11]), \
          "=r"((r)[12]),"=r"((r)[13]),"=r"((r)[14]),"=r"((r)[15]) : "r"(a))

// Stage support tile (hi+lo) SW128-swizzled; any thread count.
__device__ __forceinline__ void stage_S(char* sm, int b2, int tid, int nthr) {
    const uint4* shg = (const uint4*)g_shi + (size_t)b2 * NROW * 8;
    const uint4* slg = (const uint4*)g_slo + (size_t)b2 * NROW * 8;
    for (int k = tid; k < NROW * 8; k += nthr) {
        uint32_t dst = SWZ((uint32_t)k * 16);
        *(uint4*)(sm + SM_SHI + dst) = shg[k];
        *(uint4*)(sm + SM_SLO + dst) = slg[k];
    }
}
// Stage one 128-row Q tile (hi+lo, global tile 0..3) into buffer buf; 256 threads.
__device__ __forceinline__ void stage_Q(char* sm, int b1, int tile, int buf, int tid) {
    const uint4* qhg = (const uint4*)g_qhi + (size_t)b1 * NROW * 8;
    const uint4* qlg = (const uint4*)g_qlo + (size_t)b1 * NROW * 8;
    char* qh = sm + SM_QB + buf * 32768;
    char* ql = qh + 16384;
    for (int k = tid; k < 128 * 8; k += 256) {
        int grow = tile * 128 + (k >> 3);
        uint4 vh = make_uint4(0u, 0u, 0u, 0u), vl = vh;
        if (grow < NROW) { vh = qhg[grow * 8 + (k & 7)]; vl = qlg[grow * 8 + (k & 7)]; }
        uint32_t dst = SWZ((uint32_t)k * 16);
        *(uint4*)(qh + dst) = vh;
        *(uint4*)(ql + dst) = vl;
    }
}
// Software-pipelined epilogue over one 224-col half: while chunk k+1's LDTM is
// in flight, compute chunk k's FMNMX chain (pinned via PIN3 so ptxas cannot
// sink it). Overlaps the warp's ALU with its own TMEM reads — breaks the
// phase-locked "all load, then all compute" convoy measured in R16.
__device__ __forceinline__ void epi_half_pipe(uint32_t tmem, int h, int wid,
                                              uint32_t empty_addr,
                                              float& t0, float& t1, float& t2) {
    const uint32_t base = tmem + h * NHALF + ((wid >= 4) ? 112 : 0);
    uint32_t r0[32], r1[32], r2[32], r3[16];
    LDTM_X32(r0, base);
    TC_WAIT_LD();
    LDTM_X32(r1, base + 32);
    #pragma unroll
    for (int i = 0; i < 32; i++) ins3(t0, t1, t2, __uint_as_float(r0[i]));
    PIN3(t0, t1, t2);
    TC_WAIT_LD();
    LDTM_X32(r2, base + 64);
    #pragma unroll
    for (int i = 0; i < 32; i++) ins3(t0, t1, t2, __uint_as_float(r1[i]));
    PIN3(t0, t1, t2);
    TC_WAIT_LD();
    LDTM_X16(r3, base + 96);
    #pragma unroll
    for (int i = 0; i < 32; i++) ins3(t0, t1, t2, __uint_as_float(r2[i]));
    PIN3(t0, t1, t2);
    TC_WAIT_LD();
    // All loads retired: D half free for the producer's next MMA.
    TC_FENCE_BEFORE();
    __syncwarp();
    if (elect_one()) mbar_arrive(empty_addr);
    const bool tail = (h == 1) && (wid >= 4);   // global cols 441..447 invalid
    #pragma unroll
    for (int i = 0; i < 16; i++) {
        uint32_t b = r3[i];
        if (tail && i >= 9) b = NEGINF_BITS;
        ins3(t0, t1, t2, __uint_as_float(b));
    }
}
#endif  // HAS_TC

// ---------------------------------------------------------------------------
// Prologue: fused over both batches (grid = B1+B2). One CTA per image.
// ---------------------------------------------------------------------------
__global__ void __launch_bounds__(256, 1)
normalize_pro(const float* __restrict__ x1, const float* __restrict__ m1, int B1,
              const float* __restrict__ x2, const float* __restrict__ m2) {
    extern __shared__ float sp[];              // [64*441] + scales[448]
    const int bg = blockIdx.x, tid = threadIdx.x;
    const bool isq = (bg < B1);
    const int b = isq ? bg : bg - B1;
    const float* x  = isq ? x1 : x2;
    const float* mk = isq ? m1 : m2;
    __nv_bfloat16* hi = isq ? g_qhi : g_shi;
    __nv_bfloat16* lo = isq ? g_qlo : g_slo;
    float* scl = sp + CCH * HW;

    const float4* src = (const float4*)(x + (size_t)b * CCH * HW);
    float4* d4 = (float4*)sp;
    for (int k = tid; k < CCH * HW / 4; k += 256) d4[k] = src[k];
    __syncthreads();

    for (int i = tid; i < HW; i += 256) {
        float ss = 0.f;
        #pragma unroll
        for (int c = 0; c < CCH; c++) { float v = sp[c * HW + i]; ss += v * v; }
        scl[i] = mk[b * HW + i] * rsqrtf(ss);
    }
    __syncthreads();

    // bf16 hi/lo row-major [row][c], 16B chunks, coalesced
    for (int k = tid; k < NROW * 8; k += 256) {
        int row = k >> 3, c0 = (k & 7) * 8;
        uint4 vh, vl;
        __nv_bfloat16* ah = (__nv_bfloat16*)&vh;
        __nv_bfloat16* al = (__nv_bfloat16*)&vl;
        if (row < HW) {
            float s = scl[row];
            #pragma unroll
            for (int j = 0; j < 8; j++) {
                float v = sp[(c0 + j) * HW + row] * s;
                __nv_bfloat16 h = __float2bfloat16(v);
                ah[j] = h;
                al[j] = __float2bfloat16(v - __bfloat162float(h));
            }
        } else {
            vh = make_uint4(0u, 0u, 0u, 0u); vl = vh;
        }
        *(uint4*)(hi + ((size_t)b * NROW + row) * CCH + c0) = vh;
        *(uint4*)(lo + ((size_t)b * NROW + row) * CCH + c0) = vl;
    }

#if !HAS_TC
    // fp32 channel-major padded (fallback image only)
    float* f32 = isq ? g_qh : g_sh;
    for (int k = tid; k < CCH * HWP; k += 256) {
        int c = k / HWP, i = k - c * HWP;
        float v = (i < HW) ? sp[c * HW + i] * scl[i] : 0.f;
        f32[(size_t)b * CCH * HWP + k] = v;
    }
#endif
}

// ---------------------------------------------------------------------------
// Persistent pair kernel over HALF-PAIR units (2 M-tiles each).
// 288 threads: 8 consumer warps + 1 producer warp. Partial sums -> g_part[u].
// Pair order is b2-major: p = b2*B1 + b1 (S-tile reuse).
// ---------------------------------------------------------------------------
__global__ void __launch_bounds__(288, 1)
pair_kernel(int B1, int B2, int nunit, int ncta) {
#if HAS_TC
    extern __shared__ __align__(1024) char sm[];
    const uint32_t smb = smem_u32(sm);
    const int tid = threadIdx.x, lane = tid & 31, wid = tid >> 5;
    const int cta = blockIdx.x;
    const int u0 = (int)((long long)cta * nunit / ncta);
    const int u1 = (int)((long long)(cta + 1) * nunit / ncta);
    if (u0 >= u1) return;

    if (wid == 8) {
        asm volatile("tcgen05.alloc.cta_group::1.sync.aligned.shared::cta.b32 [%0], %1;"
                     :: "r"(smb + SM_TPTR), "r"(512u) : "memory");
        asm volatile("tcgen05.relinquish_alloc_permit.cta_group::1.sync.aligned;");
    }
    if (tid == 0) {
        mbar_init(smb + SM_FULL0, 1);  mbar_init(smb + SM_FULL1, 1);
        mbar_init(smb + SM_EMPTY0, 8); mbar_init(smb + SM_EMPTY1, 8);
        mbar_init(smb + SM_QRDY0, 8);  mbar_init(smb + SM_QRDY1, 8);
    }
    __syncthreads();
    uint32_t tmem;
    asm volatile("ld.shared.b32 %0, [%1];" : "=r"(tmem) : "r"(smb + SM_TPTR));

    // Initial staging
    int prevb2 = (u0 >> 1) / B1;
    stage_S(sm, prevb2, tid, 288);
    if (wid < 8) stage_Q(sm, (u0 >> 1) % B1, 2 * (u0 & 1), 0, tid);
    FENCE_ASYNC();
    __syncthreads();
    if (wid < 8 && elect_one()) mbar_arrive(smb + SM_QRDY0);

    int phF0 = 0, phF1 = 0;                 // consumer full waits
    int phE0 = 1, phE1 = 1;                 // producer empty waits (flipped start)
    int phQ0 = 0, phQ1 = 0;                 // producer qready waits
    float tsum = 0.f;

    for (int u = u0; u < u1; ++u) {
        const int p = u >> 1, h = u & 1;
        const int b2 = p / B1;
        if (u > u0 && b2 != prevb2) {
            __syncthreads();                 // consumers passed last FULL1 => MMAs done
            stage_S(sm, b2, tid, 288);
            FENCE_ASYNC();
            __syncthreads();
        }
        prevb2 = b2;

        if (wid == 8) {
            // -------- producer: tiles 2h, 2h+1 --------
            for (int t = 0; t < 2; t++) {
                mbar_wait(smb + (t ? SM_QRDY1 : SM_QRDY0), t ? phQ1 : phQ0);
                if (t) phQ1 ^= 1; else phQ0 ^= 1;
                const uint64_t AH = make_desc(smb + SM_QB + t * 32768);
                const uint64_t AL = make_desc(smb + SM_QB + t * 32768 + 16384);
                const uint64_t BH = make_desc(smb + SM_SHI);
                const uint64_t BL = make_desc(smb + SM_SLO);
                #pragma unroll
                for (int h2 = 0; h2 < 2; h2++) {
                    mbar_wait(smb + (h2 ? SM_EMPTY1 : SM_EMPTY0), h2 ? phE1 : phE0);
                    if (h2) phE1 ^= 1; else phE0 ^= 1;
                    TC_FENCE_AFTER();
                    if (elect_one()) {
                        const uint64_t boff = (uint64_t)h2 * 1792;
                        const uint32_t d = tmem + h2 * NHALF;
                        uint64_t pa[3] = { AH, AH, AL };
                        uint64_t pb[3] = { BH, BL, BH };
                        int first = 1;
                        #pragma unroll
                        for (int pp = 0; pp < 3; pp++)
                            #pragma unroll
                            for (int k = 0; k < 4; k++) {
                                mma_f16_ss(d, pa[pp] + k * 2, pb[pp] + boff + k * 2,
                                           MMA_IDESC, first ? 0u : 1u);
                                first = 0;
                            }
                        tc_commit(smb + (h2 ? SM_FULL1 : SM_FULL0));
                    }
                }
            }
        } else {
            // -------- consumers: tiles 2h, 2h+1 --------
            for (int t = 0; t < 2; t++) {
                const int gtile = 2 * h + t;
                float t0 = -1e30f, t1 = -1e30f, t2 = -1e30f;
                // half 0 (EMPTY0 arrive inside, after last wait::ld)
                mbar_wait(smb + SM_FULL0, phF0); phF0 ^= 1;
                TC_FENCE_AFTER();
                epi_half_pipe(tmem, 0, wid, smb + SM_EMPTY0, t0, t1, t2);
                // staging slot: next tile of this unit, or next unit's first tile
                {
                    const bool hasnext = (t == 0) || (u + 1 < u1);
                    if (hasnext) {
                        const int nu = (t == 0) ? u : u + 1;
                        const int ntile = (t == 0) ? (2 * h + 1) : 2 * (nu & 1);
                        const int nb1 = (nu >> 1) % B1;
                        stage_Q(sm, nb1, ntile, t ^ 1, tid);
                        FENCE_ASYNC();
                        __syncwarp();
                        if (elect_one()) mbar_arrive(smb + ((t ^ 1) ? SM_QRDY1 : SM_QRDY0));
                    }
                }
                // half 1 (EMPTY1 arrive inside)
                mbar_wait(smb + SM_FULL1, phF1); phF1 ^= 1;
                TC_FENCE_AFTER();
                epi_half_pipe(tmem, 1, wid, smb + SM_EMPTY1, t0, t1, t2);
                // merge column-halves per row
                float* mg = (float*)(sm + SM_MERGE);
                const int r = (wid & 3) * 32 + lane;
                if (wid >= 4) { mg[r * 3] = t0; mg[r * 3 + 1] = t1; mg[r * 3 + 2] = t2; }
                BAR_CONS();
                if (wid < 4) {
                    ins3(t0, t1, t2, mg[r * 3]);
                    ins3(t0, t1, t2, mg[r * 3 + 1]);
                    ins3(t0, t1, t2, mg[r * 3 + 2]);
                    const int grow = gtile * 128 + r;
                    if (grow < HW) tsum += t0 + t1 + t2;
                }
                BAR_CONS();
            }
            // unit output -> g_part[u]
            if (wid < 4) {
                float s = tsum;
                #pragma unroll
                for (int off = 16; off; off >>= 1) s += __shfl_xor_sync(0xffffffffu, s, off);
                if (lane == 0) ((float*)(sm + SM_WSUM))[wid] = s;
            }
            BAR_CONS();
            if (tid == 0) {
                const float* ws = (const float*)(sm + SM_WSUM);
                g_part[u] = ws[0] + ws[1] + ws[2] + ws[3];
            }
            BAR_CONS();
            tsum = 0.f;
        }
    }

    __syncthreads();
    if (wid == 8) {
        asm volatile("tcgen05.dealloc.cta_group::1.sync.aligned.b32 %0, %1;"
                     :: "r"(tmem), "r"(512u));
    }

#else  // ---------------- correctness-only fallback (never selected at runtime) ----------------
    __shared__ float red[288];
    const int tid = threadIdx.x;
    const int cta = blockIdx.x;
    const int u0 = (int)((long long)cta * nunit / ncta);
    const int u1 = (int)((long long)(cta + 1) * nunit / ncta);
    for (int u = u0; u < u1; ++u) {
        const int p = u >> 1, h = u & 1;
        const int b2 = p / B1, b1 = p - b2 * B1;
        const float* qg = g_qh + (size_t)b1 * CCH * HWP;
        const float* sg = g_sh + (size_t)b2 * CCH * HWP;
        const int r0 = h * 256, r1 = (h * 256 + 256 < HW) ? h * 256 + 256 : HW;
        float part = 0.f;
        for (int r = r0 + tid; r < r1; r += blockDim.x) {
            float t0 = -1e30f, t1 = -1e30f, t2 = -1e30f;
            for (int j = 0; j < HW; j++) {
                float d = 0.f;
                for (int c = 0; c < CCH; c++) d += qg[c * HWP + r] * sg[c * HWP + j];
                ins3(t0, t1, t2, d);
            }
            part += t0 + t1 + t2;
        }
        red[tid] = part;
        __syncthreads();
        if (tid == 0) {
            float s = 0.f;
            for (int k = 0; k < (int)blockDim.x; k++) s += red[k];
            g_part[u] = s;
        }
        __syncthreads();
    }
#endif
}

// ---------------------------------------------------------------------------
// Final: units are b2-major (p = b2*B1 + b1); output is out[b1*B2 + b2].
// (R9/R10 bug was writing out[p] — transposed output.)
// ---------------------------------------------------------------------------
__global__ void sum_units(float* __restrict__ out, int B1, int B2, int npair) {
    int p = blockIdx.x * blockDim.x + threadIdx.x;
    if (p < npair) {
        int b2 = p / B1, b1 = p - b2 * B1;
        out[b1 * B2 + b2] = g_part[2 * p] + g_part[2 * p + 1];
    }
}

// ---------------------------------------------------------------------------
// Launch
// ---------------------------------------------------------------------------
extern "C" void kernel_launch(void* const* d_in, const int* in_sizes, int n_in,
                              void* d_out, int out_size) {
    const float* x1 = (const float*)d_in[0];
    const float* x2 = (const float*)d_in[1];
    const float* m1 = (const float*)d_in[2];
    const float* m2 = (const float*)d_in[3];
    float* out = (float*)d_out;

    int B1 = in_sizes[0] / (CCH * HW);
    int B2 = in_sizes[1] / (CCH * HW);
    if (B1 > B1MAX) B1 = B1MAX;
    if (B2 > B2MAX) B2 = B2MAX;

    const int pro_smem = (CCH * HW + HWP) * (int)sizeof(float);   // 114688
    cudaFuncSetAttribute(normalize_pro,
                         cudaFuncAttributeMaxDynamicSharedMemorySize, pro_smem);
    normalize_pro<<<B1 + B2, 256, pro_smem>>>(x1, m1, B1, x2, m2);

    const int npair = B1 * B2;
    const int nunit = npair * 2;
    int ncta = nunit < 148 ? nunit : 148;
    cudaFuncSetAttribute(pair_kernel,
                         cudaFuncAttributeMaxDynamicSharedMemorySize, SM_TOTAL);
    pair_kernel<<<ncta, 288, SM_TOTAL>>>(B1, B2, nunit, ncta);

    sum_units<<<(npair + 255) / 256, 256>>>(out, B1, B2, npair);
}